// round 4
// baseline (speedup 1.0000x reference)
#include <cuda_runtime.h>
#include <cuda_bf16.h>
#include <math.h>
#include <stdint.h>

#define S_LEN 1024
#define BSZ   32
#define CIN   512
#define NH    8
#define HD    64
#define NQ    1544
#define NQP   1664            // 13 * 128 padded
#define NROWS 32768
#define PACK  200
#define CH    8
#define NCHUNK (S_LEN / CH)

// ---------------------------------------------------------------------------
// Scratch (device globals; no allocation allowed)
// ---------------------------------------------------------------------------
__device__ __align__(16) __nv_bfloat16 g_h0[(size_t)NROWS * CIN];
__device__ __align__(16) __nv_bfloat16 g_h1[(size_t)NROWS * CIN];
__device__ __align__(16) float         g_qkvb[(size_t)NROWS * NQP];
__device__ __align__(16) __nv_bfloat16 g_B0[(size_t)NQP * CIN];
__device__ __align__(16) __nv_bfloat16 g_B1[(size_t)NQP * CIN];
__device__ __align__(16) __nv_bfloat16 g_W0[(size_t)CIN * CIN];
__device__ __align__(16) __nv_bfloat16 g_W1[(size_t)CIN * CIN];
__device__ __align__(16) float         g_packed[(size_t)BSZ * NH * S_LEN * PACK];
__device__ __align__(16) __nv_bfloat16 g_o0[(size_t)NROWS * CIN];
__device__ __align__(16) __nv_bfloat16 g_o1[(size_t)NROWS * CIN];

// ---------------------------------------------------------------------------
// Helpers (compute_100-safe: cp.async / ldmatrix / mma.sync only)
// ---------------------------------------------------------------------------
__device__ __forceinline__ uint32_t smem_u32(const void* p) {
    uint32_t a;
    asm("{ .reg .u64 t; cvta.to.shared.u64 t, %1; cvt.u32.u64 %0, t; }" : "=r"(a) : "l"(p));
    return a;
}
#define CP_ASYNC16(saddr, gptr) \
    asm volatile("cp.async.cg.shared.global [%0], [%1], 16;" :: "r"(saddr), "l"(gptr) : "memory")
#define CP_COMMIT() asm volatile("cp.async.commit_group;" ::: "memory")
#define CP_WAIT(n)  asm volatile("cp.async.wait_group %0;" :: "n"(n) : "memory")

#define LDMATRIX_X4(r, addr) \
    asm volatile("ldmatrix.sync.aligned.m8n8.x4.shared.b16 {%0,%1,%2,%3}, [%4];" \
        : "=r"((r)[0]), "=r"((r)[1]), "=r"((r)[2]), "=r"((r)[3]) : "r"(addr))

#define MMA_BF16(d, a, b0, b1) \
    asm volatile("mma.sync.aligned.m16n8k16.row.col.f32.bf16.bf16.f32 " \
        "{%0,%1,%2,%3}, {%4,%5,%6,%7}, {%8,%9}, {%0,%1,%2,%3};" \
        : "+f"((d)[0]), "+f"((d)[1]), "+f"((d)[2]), "+f"((d)[3]) \
        : "r"((a)[0]), "r"((a)[1]), "r"((a)[2]), "r"((a)[3]), "r"(b0), "r"(b1))

#define SW128(off) ((off) ^ (((off) >> 3) & 0x70))

__device__ __forceinline__ void split1(float a, __nv_bfloat16& hi, __nv_bfloat16& lo) {
    hi = __float2bfloat16(a);
    lo = __float2bfloat16(a - __bfloat162float(hi));
}
__device__ __forceinline__ uint32_t pack2(__nv_bfloat16 a, __nv_bfloat16 b) {
    return (uint32_t)__bfloat16_as_ushort(a) | ((uint32_t)__bfloat16_as_ushort(b) << 16);
}

// ---------------------------------------------------------------------------
// 1) LayerNorm fused with bf16 hi/lo split
// ---------------------------------------------------------------------------
__global__ void __launch_bounds__(256) ln_kernel(
    const float* __restrict__ x, const float* __restrict__ gamma,
    const float* __restrict__ beta,
    __nv_bfloat16* __restrict__ h0, __nv_bfloat16* __restrict__ h1)
{
    int lane = threadIdx.x & 31;
    int row  = (blockIdx.x << 3) + (threadIdx.x >> 5);
    const float4* xr = (const float4*)(x + (size_t)row * CIN);
    float4 v[4];
    float s = 0.f, ss = 0.f;
#pragma unroll
    for (int i = 0; i < 4; ++i) {
        v[i] = xr[lane + (i << 5)];
        s  += v[i].x + v[i].y + v[i].z + v[i].w;
        ss += v[i].x * v[i].x + v[i].y * v[i].y + v[i].z * v[i].z + v[i].w * v[i].w;
    }
#pragma unroll
    for (int o = 16; o; o >>= 1) {
        s  += __shfl_xor_sync(0xffffffffu, s,  o);
        ss += __shfl_xor_sync(0xffffffffu, ss, o);
    }
    float mean = s * (1.f / CIN);
    float var  = ss * (1.f / CIN) - mean * mean;
    float inv  = rsqrtf(var + 1e-5f);
    uint32_t* r0 = (uint32_t*)(h0 + (size_t)row * CIN);
    uint32_t* r1 = (uint32_t*)(h1 + (size_t)row * CIN);
    const float4* g4 = (const float4*)gamma;
    const float4* b4 = (const float4*)beta;
#pragma unroll
    for (int i = 0; i < 4; ++i) {
        int c = lane + (i << 5);
        float4 g = g4[c], b = b4[c];
        float o0 = (v[i].x - mean) * inv * g.x + b.x;
        float o1 = (v[i].y - mean) * inv * g.y + b.y;
        float o2 = (v[i].z - mean) * inv * g.z + b.z;
        float o3 = (v[i].w - mean) * inv * g.w + b.w;
        __nv_bfloat16 a0, a1, b0h, b1h, c0, c1, d0, d1;
        split1(o0, a0, a1); split1(o1, b0h, b1h); split1(o2, c0, c1); split1(o3, d0, d1);
        r0[c * 2]     = pack2(a0, b0h);
        r0[c * 2 + 1] = pack2(c0, d0);
        r1[c * 2]     = pack2(a1, b1h);
        r1[c * 2 + 1] = pack2(c1, d1);
    }
}

// ---------------------------------------------------------------------------
// Weight conversion: transpose to [N, K] and split hi/lo (padded with zeros)
// ---------------------------------------------------------------------------
__global__ void __launch_bounds__(256) conv_wslow(
    const float* __restrict__ w, __nv_bfloat16* __restrict__ b0,
    __nv_bfloat16* __restrict__ b1)
{
    int idx = blockIdx.x * 256 + threadIdx.x;
    if (idx >= NQP * CIN) return;
    int n = idx / CIN, k = idx % CIN;
    float v = (n < NQ) ? w[(size_t)k * NQ + n] : 0.f;
    __nv_bfloat16 hi, lo; split1(v, hi, lo);
    b0[idx] = hi; b1[idx] = lo;
}
__global__ void __launch_bounds__(256) conv_wout(
    const float* __restrict__ w, __nv_bfloat16* __restrict__ b0,
    __nv_bfloat16* __restrict__ b1)
{
    int idx = blockIdx.x * 256 + threadIdx.x;
    if (idx >= CIN * CIN) return;
    int n = idx / CIN, k = idx % CIN;
    float v = w[(size_t)k * CIN + n];
    __nv_bfloat16 hi, lo; split1(v, hi, lo);
    b0[idx] = hi; b1[idx] = lo;
}

// ---------------------------------------------------------------------------
// mma.sync GEMM: C[32768, ldc] = (A0+A1) @ (B0+B1)^T via 3-pass bf16 split.
// Tile 128x128, BK=64, 3-stage cp.async pipeline, fragment reuse across the
// three passes (A0B0 + A0B1 + A1B0 share one fp32 accumulator).
// ---------------------------------------------------------------------------
#define STG_BYTES 65536   // 4 buffers * 16KB per stage

template <bool RES>
__global__ void __launch_bounds__(256) gemm_mma(
    const __nv_bfloat16* __restrict__ A0, const __nv_bfloat16* __restrict__ A1,
    const __nv_bfloat16* __restrict__ B0, const __nv_bfloat16* __restrict__ B1,
    const float* __restrict__ res, float* __restrict__ C, int ldc)
{
    extern __shared__ __align__(1024) char smem[];
    const uint32_t sb = smem_u32(smem);
    const int tid = threadIdx.x, wid = tid >> 5, lane = tid & 31;
    const int row0 = blockIdx.y << 7, col0 = blockIdx.x << 7;
    const int wm = (wid & 3) << 5;   // warp m offset
    const int wn = (wid >> 2) << 6;  // warp n offset

    float acc[2][8][4];
#pragma unroll
    for (int i = 0; i < 2; ++i)
#pragma unroll
        for (int j = 0; j < 8; ++j)
#pragma unroll
            for (int q = 0; q < 4; ++q) acc[i][j][q] = 0.f;

    const __nv_bfloat16* gsrc[4] = {
        A0 + (size_t)row0 * CIN, A1 + (size_t)row0 * CIN,
        B0 + (size_t)col0 * CIN, B1 + (size_t)col0 * CIN };
    int lrow[4], lcole[4];
    uint32_t soff[4];
#pragma unroll
    for (int l = 0; l < 4; ++l) {
        int idx = tid + (l << 8);
        lrow[l]  = idx >> 3;
        int cb   = (idx & 7) << 4;
        lcole[l] = cb >> 1;
        soff[l]  = SW128((lrow[l] << 7) + cb);
    }

    uint32_t arow[2], brow[4];
#pragma unroll
    for (int mf = 0; mf < 2; ++mf)
        arow[mf] = (uint32_t)(wm + (mf << 4) + (lane & 15)) << 7;
    const uint32_t abyte = ((lane >> 4) << 4);
#pragma unroll
    for (int nf = 0; nf < 4; ++nf)
        brow[nf] = (uint32_t)(wn + (nf << 4) + (lane & 7) + ((lane >> 4) << 3)) << 7;
    const uint32_t bbyte = (((lane >> 3) & 1) << 4);

#define PREFETCH(stage, kc) do { \
    uint32_t stb_ = sb + (stage) * STG_BYTES; \
    int ke = (kc) << 6; \
    _Pragma("unroll") \
    for (int b_ = 0; b_ < 4; ++b_) { \
        const __nv_bfloat16* gp = gsrc[b_]; \
        _Pragma("unroll") \
        for (int l_ = 0; l_ < 4; ++l_) \
            CP_ASYNC16(stb_ + b_ * 16384 + soff[l_], \
                       gp + (size_t)lrow[l_] * CIN + ke + lcole[l_]); \
    } \
    CP_COMMIT(); \
} while (0)

    PREFETCH(0, 0);
    PREFETCH(1, 1);

#pragma unroll
    for (int kc = 0; kc < 8; ++kc) {
        if (kc + 2 < 8) { PREFETCH((kc + 2) % 3, kc + 2); } else { CP_COMMIT(); }
        CP_WAIT(2);
        __syncthreads();

        uint32_t stb = sb + (kc % 3) * STG_BYTES;
#pragma unroll
        for (int kf = 0; kf < 4; ++kf) {
            uint32_t kb = (uint32_t)(kf << 5);
            uint32_t af0[2][4], af1[2][4], bf0[4][4], bf1[4][4];
#pragma unroll
            for (int mf = 0; mf < 2; ++mf) {
                LDMATRIX_X4(af0[mf], stb + SW128(arow[mf] + kb + abyte));
                LDMATRIX_X4(af1[mf], stb + 16384u + SW128(arow[mf] + kb + abyte));
            }
#pragma unroll
            for (int nf = 0; nf < 4; ++nf) {
                LDMATRIX_X4(bf0[nf], stb + 32768u + SW128(brow[nf] + kb + bbyte));
                LDMATRIX_X4(bf1[nf], stb + 49152u + SW128(brow[nf] + kb + bbyte));
            }
#pragma unroll
            for (int mf = 0; mf < 2; ++mf)
#pragma unroll
                for (int nf = 0; nf < 4; ++nf) {
                    MMA_BF16(acc[mf][2 * nf],     af0[mf], bf0[nf][0], bf0[nf][1]);
                    MMA_BF16(acc[mf][2 * nf + 1], af0[mf], bf0[nf][2], bf0[nf][3]);
                    MMA_BF16(acc[mf][2 * nf],     af0[mf], bf1[nf][0], bf1[nf][1]);
                    MMA_BF16(acc[mf][2 * nf + 1], af0[mf], bf1[nf][2], bf1[nf][3]);
                    MMA_BF16(acc[mf][2 * nf],     af1[mf], bf0[nf][0], bf0[nf][1]);
                    MMA_BF16(acc[mf][2 * nf + 1], af1[mf], bf0[nf][2], bf0[nf][3]);
                }
        }
        __syncthreads();
    }

#pragma unroll
    for (int mf = 0; mf < 2; ++mf) {
        size_t r = (size_t)row0 + wm + (mf << 4) + (lane >> 2);
#pragma unroll
        for (int nfr = 0; nfr < 8; ++nfr) {
            int n = col0 + wn + (nfr << 3) + ((lane & 3) << 1);
            float2 v0 = make_float2(acc[mf][nfr][0], acc[mf][nfr][1]);
            float2 v1 = make_float2(acc[mf][nfr][2], acc[mf][nfr][3]);
            if (RES) {
                float2 r0 = *(const float2*)(res + r * ldc + n);
                float2 r1 = *(const float2*)(res + (r + 8) * ldc + n);
                v0.x += r0.x; v0.y += r0.y; v1.x += r1.x; v1.y += r1.y;
            }
            *(float2*)(C + r * ldc + n) = v0;
            *(float2*)(C + (r + 8) * ldc + n) = v1;
        }
    }
}

// ---------------------------------------------------------------------------
// 3) Pointwise transform + repack time-major per (b,h)
// ---------------------------------------------------------------------------
__device__ __forceinline__ float elu_p1(float v) {
    return v > 0.f ? v + 1.f : expf(v);
}
__global__ void __launch_bounds__(256) transform_kernel(
    const float* __restrict__ qkvb, float* __restrict__ packed)
{
    int r = blockIdx.x;
    int h = threadIdx.x >> 5;
    int lane = threadIdx.x & 31;
    int s = r >> 5, b = r & 31;
    const float* in = qkvb + (size_t)r * NQP + h * 193;

    float q1 = elu_p1(in[lane]),      q2 = elu_p1(in[lane + 32]);
    float k1 = elu_p1(in[64 + lane]), k2 = elu_p1(in[96 + lane]);
    float qs = q1 + q2, ks = k1 + k2;
#pragma unroll
    for (int o = 16; o; o >>= 1) {
        qs += __shfl_xor_sync(0xffffffffu, qs, o);
        ks += __shfl_xor_sync(0xffffffffu, ks, o);
    }
    float v1 = in[128 + lane], v2 = in[160 + lane];
    float bt = in[192];

    float* out = packed + ((size_t)(b * NH + h) * S_LEN + s) * PACK;
    float qi = 1.f / qs, ki = 1.f / ks;
    out[lane]       = q1 * qi;  out[lane + 32]  = q2 * qi;
    out[64 + lane]  = k1 * ki;  out[96 + lane]  = k2 * ki;
    out[128 + lane] = v1;       out[160 + lane] = v2;
    if (lane == 0) out[192] = 1.f / (1.f + expf(-bt));
}

// ---------------------------------------------------------------------------
// 4) Delta-rule scan: 256 threads/block, thread = (row, quarter).
//    Key identity: o = W_old q + u * (k·q), so both dots share one pass and
//    the rank-1 update leaves the critical path.
// ---------------------------------------------------------------------------
__global__ void __launch_bounds__(256) scan_kernel(
    const float* __restrict__ packed,
    __nv_bfloat16* __restrict__ o0, __nv_bfloat16* __restrict__ o1)
{
    __shared__ __align__(16) float sbuf[2][CH * PACK];
    int bh = blockIdx.x;
    int b = bh >> 3, h = bh & 7;
    int tid = threadIdx.x;
    int row = tid >> 2, qd = tid & 3;       // quarter: j in [qd*16, qd*16+16)

    const float4* base = (const float4*)(packed + (size_t)bh * S_LEN * PACK);
    float4 pre0, pre1;
    pre0 = base[tid];
    if (tid < 144) pre1 = base[tid + 256];
    ((float4*)sbuf[0])[tid] = pre0;
    if (tid < 144) ((float4*)sbuf[0])[tid + 256] = pre1;

    float w[16];
#pragma unroll
    for (int j = 0; j < 16; ++j) w[j] = 0.f;
    __syncthreads();

    __nv_bfloat16* ob0 = o0 + (size_t)b * 512 + h * 64 + row;
    __nv_bfloat16* ob1 = o1 + (size_t)b * 512 + h * 64 + row;

    for (int c = 0; c < NCHUNK; ++c) {
        const float* cp0 = sbuf[c & 1];
        if (c + 1 < NCHUNK) {
            const float4* nb = base + (size_t)(c + 1) * (CH * PACK / 4);
            pre0 = nb[tid];
            if (tid < 144) pre1 = nb[tid + 256];
        }
#pragma unroll
        for (int st = 0; st < CH; ++st) {
            const float* sp = cp0 + st * PACK;
            int t = (c << 3) + st;
            const float4* qp = (const float4*)(sp + (qd << 4));
            const float4* kp = (const float4*)(sp + 64 + (qd << 4));
            float kk[16], qq[16];
#pragma unroll
            for (int j4 = 0; j4 < 4; ++j4) {
                float4 k4 = kp[j4], q4 = qp[j4];
                kk[4*j4+0] = k4.x; kk[4*j4+1] = k4.y; kk[4*j4+2] = k4.z; kk[4*j4+3] = k4.w;
                qq[4*j4+0] = q4.x; qq[4*j4+1] = q4.y; qq[4*j4+2] = q4.z; qq[4*j4+3] = q4.w;
            }
            float pk = 0.f, pq = 0.f, pkq = 0.f;
#pragma unroll
            for (int j = 0; j < 16; ++j) {
                pk  += w[j] * kk[j];
                pq  += w[j] * qq[j];
                pkq += kk[j] * qq[j];
            }
#pragma unroll
            for (int off = 1; off <= 2; off <<= 1) {
                pk  += __shfl_xor_sync(0xffffffffu, pk,  off);
                pq  += __shfl_xor_sync(0xffffffffu, pq,  off);
                pkq += __shfl_xor_sync(0xffffffffu, pkq, off);
            }
            float u  = sp[192] * (sp[128 + row] - pk);
            float oi = pq + u * pkq;
#pragma unroll
            for (int j = 0; j < 16; ++j) w[j] += u * kk[j];
            if (qd == 0) {
                __nv_bfloat16 hi = __float2bfloat16(oi);
                __nv_bfloat16 lo = __float2bfloat16(oi - __bfloat162float(hi));
                ob0[(size_t)t * (BSZ * 512)] = hi;
                ob1[(size_t)t * (BSZ * 512)] = lo;
            }
        }
        if (c + 1 < NCHUNK) {
            float4* db = (float4*)sbuf[(c + 1) & 1];
            db[tid] = pre0;
            if (tid < 144) db[tid + 256] = pre1;
        }
        __syncthreads();
    }
}

// ---------------------------------------------------------------------------
// Launch
// ---------------------------------------------------------------------------
static const int SMEM_GEMM = 3 * STG_BYTES;   // 192KB

extern "C" void kernel_launch(void* const* d_in, const int* in_sizes, int n_in,
                              void* d_out, int out_size)
{
    const float* x     = (const float*)d_in[0];
    const float* gamma = (const float*)d_in[1];
    const float* beta  = (const float*)d_in[2];
    const float* wslow = (const float*)d_in[3];
    const float* wout  = (const float*)d_in[4];
    float* out = (float*)d_out;

    __nv_bfloat16 *h0, *h1, *B0, *B1, *W0, *W1, *o0, *o1;
    float *qkvb, *packed;
    cudaGetSymbolAddress((void**)&h0, g_h0);
    cudaGetSymbolAddress((void**)&h1, g_h1);
    cudaGetSymbolAddress((void**)&qkvb, g_qkvb);
    cudaGetSymbolAddress((void**)&B0, g_B0);
    cudaGetSymbolAddress((void**)&B1, g_B1);
    cudaGetSymbolAddress((void**)&W0, g_W0);
    cudaGetSymbolAddress((void**)&W1, g_W1);
    cudaGetSymbolAddress((void**)&packed, g_packed);
    cudaGetSymbolAddress((void**)&o0, g_o0);
    cudaGetSymbolAddress((void**)&o1, g_o1);

    cudaFuncSetAttribute(gemm_mma<false>, cudaFuncAttributeMaxDynamicSharedMemorySize, SMEM_GEMM);
    cudaFuncSetAttribute(gemm_mma<true>,  cudaFuncAttributeMaxDynamicSharedMemorySize, SMEM_GEMM);

    ln_kernel<<<NROWS / 8, 256>>>(x, gamma, beta, h0, h1);
    conv_wslow<<<(NQP * CIN + 255) / 256, 256>>>(wslow, B0, B1);
    conv_wout<<<(CIN * CIN + 255) / 256, 256>>>(wout, W0, W1);
    gemm_mma<false><<<dim3(NQP / 128, NROWS / 128), 256, SMEM_GEMM>>>(
        h0, h1, B0, B1, nullptr, qkvb, NQP);
    transform_kernel<<<NROWS, 256>>>(qkvb, packed);
    scan_kernel<<<BSZ * NH, 256>>>(packed, o0, o1);
    gemm_mma<true><<<dim3(4, NROWS / 128), 256, SMEM_GEMM>>>(
        o0, o1, W0, W1, x, out, CIN);
}

// round 5
// speedup vs baseline: 1.3229x; 1.3229x over previous
#include <cuda_runtime.h>
#include <cuda_bf16.h>
#include <math.h>
#include <stdint.h>

#define S_LEN 1024
#define BSZ   32
#define CIN   512
#define NH    8
#define HD    64
#define NQ    1544
#define NQP   1664            // 13 * 128 padded
#define NROWS 32768
#define PACK  200
#define CH    8
#define NCHUNK (S_LEN / CH)

// ---------------------------------------------------------------------------
// Scratch (device globals; no allocation allowed)
// ---------------------------------------------------------------------------
__device__ __align__(16) __nv_bfloat16 g_h0[(size_t)NROWS * CIN];
__device__ __align__(16) __nv_bfloat16 g_h1[(size_t)NROWS * CIN];
__device__ __align__(16) float         g_qkvb[(size_t)NROWS * NQP];
__device__ __align__(16) __nv_bfloat16 g_B0[(size_t)NQP * CIN];
__device__ __align__(16) __nv_bfloat16 g_B1[(size_t)NQP * CIN];
__device__ __align__(16) __nv_bfloat16 g_W0[(size_t)CIN * CIN];
__device__ __align__(16) __nv_bfloat16 g_W1[(size_t)CIN * CIN];
__device__ __align__(16) float         g_packed[(size_t)BSZ * NH * S_LEN * PACK];
__device__ __align__(16) __nv_bfloat16 g_o0[(size_t)NROWS * CIN];
__device__ __align__(16) __nv_bfloat16 g_o1[(size_t)NROWS * CIN];

// ---------------------------------------------------------------------------
// Helpers (compute_100-safe: cp.async / ldmatrix / mma.sync only)
// ---------------------------------------------------------------------------
__device__ __forceinline__ uint32_t smem_u32(const void* p) {
    uint32_t a;
    asm("{ .reg .u64 t; cvta.to.shared.u64 t, %1; cvt.u32.u64 %0, t; }" : "=r"(a) : "l"(p));
    return a;
}
#define CP_ASYNC16(saddr, gptr) \
    asm volatile("cp.async.cg.shared.global [%0], [%1], 16;" :: "r"(saddr), "l"(gptr) : "memory")
#define CP_COMMIT() asm volatile("cp.async.commit_group;" ::: "memory")
#define CP_WAIT(n)  asm volatile("cp.async.wait_group %0;" :: "n"(n) : "memory")

#define LDMATRIX_X4(r, addr) \
    asm volatile("ldmatrix.sync.aligned.m8n8.x4.shared.b16 {%0,%1,%2,%3}, [%4];" \
        : "=r"((r)[0]), "=r"((r)[1]), "=r"((r)[2]), "=r"((r)[3]) : "r"(addr))

#define MMA_BF16(d, a, b0, b1) \
    asm volatile("mma.sync.aligned.m16n8k16.row.col.f32.bf16.bf16.f32 " \
        "{%0,%1,%2,%3}, {%4,%5,%6,%7}, {%8,%9}, {%0,%1,%2,%3};" \
        : "+f"((d)[0]), "+f"((d)[1]), "+f"((d)[2]), "+f"((d)[3]) \
        : "r"((a)[0]), "r"((a)[1]), "r"((a)[2]), "r"((a)[3]), "r"(b0), "r"(b1))

#define SW128(off) ((off) ^ (((off) >> 3) & 0x70))

__device__ __forceinline__ void split1(float a, __nv_bfloat16& hi, __nv_bfloat16& lo) {
    hi = __float2bfloat16(a);
    lo = __float2bfloat16(a - __bfloat162float(hi));
}
__device__ __forceinline__ uint32_t pack2(__nv_bfloat16 a, __nv_bfloat16 b) {
    return (uint32_t)__bfloat16_as_ushort(a) | ((uint32_t)__bfloat16_as_ushort(b) << 16);
}

// ---------------------------------------------------------------------------
// 1) LayerNorm fused with bf16 hi/lo split
// ---------------------------------------------------------------------------
__global__ void __launch_bounds__(256) ln_kernel(
    const float* __restrict__ x, const float* __restrict__ gamma,
    const float* __restrict__ beta,
    __nv_bfloat16* __restrict__ h0, __nv_bfloat16* __restrict__ h1)
{
    int lane = threadIdx.x & 31;
    int row  = (blockIdx.x << 3) + (threadIdx.x >> 5);
    const float4* xr = (const float4*)(x + (size_t)row * CIN);
    float4 v[4];
    float s = 0.f, ss = 0.f;
#pragma unroll
    for (int i = 0; i < 4; ++i) {
        v[i] = xr[lane + (i << 5)];
        s  += v[i].x + v[i].y + v[i].z + v[i].w;
        ss += v[i].x * v[i].x + v[i].y * v[i].y + v[i].z * v[i].z + v[i].w * v[i].w;
    }
#pragma unroll
    for (int o = 16; o; o >>= 1) {
        s  += __shfl_xor_sync(0xffffffffu, s,  o);
        ss += __shfl_xor_sync(0xffffffffu, ss, o);
    }
    float mean = s * (1.f / CIN);
    float var  = ss * (1.f / CIN) - mean * mean;
    float inv  = rsqrtf(var + 1e-5f);
    uint32_t* r0 = (uint32_t*)(h0 + (size_t)row * CIN);
    uint32_t* r1 = (uint32_t*)(h1 + (size_t)row * CIN);
    const float4* g4 = (const float4*)gamma;
    const float4* b4 = (const float4*)beta;
#pragma unroll
    for (int i = 0; i < 4; ++i) {
        int c = lane + (i << 5);
        float4 g = g4[c], b = b4[c];
        float o0 = (v[i].x - mean) * inv * g.x + b.x;
        float o1 = (v[i].y - mean) * inv * g.y + b.y;
        float o2 = (v[i].z - mean) * inv * g.z + b.z;
        float o3 = (v[i].w - mean) * inv * g.w + b.w;
        __nv_bfloat16 a0, a1, b0h, b1h, c0, c1, d0, d1;
        split1(o0, a0, a1); split1(o1, b0h, b1h); split1(o2, c0, c1); split1(o3, d0, d1);
        r0[c * 2]     = pack2(a0, b0h);
        r0[c * 2 + 1] = pack2(c0, d0);
        r1[c * 2]     = pack2(a1, b1h);
        r1[c * 2 + 1] = pack2(c1, d1);
    }
}

// ---------------------------------------------------------------------------
// Weight conversion: transpose to [N, K] and split hi/lo (padded with zeros)
// ---------------------------------------------------------------------------
__global__ void __launch_bounds__(256) conv_wslow(
    const float* __restrict__ w, __nv_bfloat16* __restrict__ b0,
    __nv_bfloat16* __restrict__ b1)
{
    int idx = blockIdx.x * 256 + threadIdx.x;
    if (idx >= NQP * CIN) return;
    int n = idx / CIN, k = idx % CIN;
    float v = (n < NQ) ? w[(size_t)k * NQ + n] : 0.f;
    __nv_bfloat16 hi, lo; split1(v, hi, lo);
    b0[idx] = hi; b1[idx] = lo;
}
__global__ void __launch_bounds__(256) conv_wout(
    const float* __restrict__ w, __nv_bfloat16* __restrict__ b0,
    __nv_bfloat16* __restrict__ b1)
{
    int idx = blockIdx.x * 256 + threadIdx.x;
    if (idx >= CIN * CIN) return;
    int n = idx / CIN, k = idx % CIN;
    float v = w[(size_t)k * CIN + n];
    __nv_bfloat16 hi, lo; split1(v, hi, lo);
    b0[idx] = hi; b1[idx] = lo;
}

// ---------------------------------------------------------------------------
// mma.sync GEMM: C[32768, ldc] = (A0+A1) @ (B0+B1)^T via 3-pass bf16 split.
// Tile 128x128, BK=64, 3-stage cp.async pipeline, fragment reuse across the
// three passes (A0B0 + A0B1 + A1B0 share one fp32 accumulator).
// ---------------------------------------------------------------------------
#define STG_BYTES 65536   // 4 buffers * 16KB per stage

template <bool RES>
__global__ void __launch_bounds__(256) gemm_mma(
    const __nv_bfloat16* __restrict__ A0, const __nv_bfloat16* __restrict__ A1,
    const __nv_bfloat16* __restrict__ B0, const __nv_bfloat16* __restrict__ B1,
    const float* __restrict__ res, float* __restrict__ C, int ldc)
{
    extern __shared__ __align__(1024) char smem[];
    const uint32_t sb = smem_u32(smem);
    const int tid = threadIdx.x, wid = tid >> 5, lane = tid & 31;
    const int row0 = blockIdx.y << 7, col0 = blockIdx.x << 7;
    const int wm = (wid & 3) << 5;   // warp m offset
    const int wn = (wid >> 2) << 6;  // warp n offset

    float acc[2][8][4];
#pragma unroll
    for (int i = 0; i < 2; ++i)
#pragma unroll
        for (int j = 0; j < 8; ++j)
#pragma unroll
            for (int q = 0; q < 4; ++q) acc[i][j][q] = 0.f;

    const __nv_bfloat16* gsrc[4] = {
        A0 + (size_t)row0 * CIN, A1 + (size_t)row0 * CIN,
        B0 + (size_t)col0 * CIN, B1 + (size_t)col0 * CIN };
    int lrow[4], lcole[4];
    uint32_t soff[4];
#pragma unroll
    for (int l = 0; l < 4; ++l) {
        int idx = tid + (l << 8);
        lrow[l]  = idx >> 3;
        int cb   = (idx & 7) << 4;
        lcole[l] = cb >> 1;
        soff[l]  = SW128((lrow[l] << 7) + cb);
    }

    uint32_t arow[2], brow[4];
#pragma unroll
    for (int mf = 0; mf < 2; ++mf)
        arow[mf] = (uint32_t)(wm + (mf << 4) + (lane & 15)) << 7;
    const uint32_t abyte = ((lane >> 4) << 4);
#pragma unroll
    for (int nf = 0; nf < 4; ++nf)
        brow[nf] = (uint32_t)(wn + (nf << 4) + (lane & 7) + ((lane >> 4) << 3)) << 7;
    const uint32_t bbyte = (((lane >> 3) & 1) << 4);

#define PREFETCH(stage, kc) do { \
    uint32_t stb_ = sb + (stage) * STG_BYTES; \
    int ke = (kc) << 6; \
    _Pragma("unroll") \
    for (int b_ = 0; b_ < 4; ++b_) { \
        const __nv_bfloat16* gp = gsrc[b_]; \
        _Pragma("unroll") \
        for (int l_ = 0; l_ < 4; ++l_) \
            CP_ASYNC16(stb_ + b_ * 16384 + soff[l_], \
                       gp + (size_t)lrow[l_] * CIN + ke + lcole[l_]); \
    } \
    CP_COMMIT(); \
} while (0)

    PREFETCH(0, 0);
    PREFETCH(1, 1);

#pragma unroll
    for (int kc = 0; kc < 8; ++kc) {
        if (kc + 2 < 8) { PREFETCH((kc + 2) % 3, kc + 2); } else { CP_COMMIT(); }
        CP_WAIT(2);
        __syncthreads();

        uint32_t stb = sb + (kc % 3) * STG_BYTES;
#pragma unroll
        for (int kf = 0; kf < 4; ++kf) {
            uint32_t kb = (uint32_t)(kf << 5);
            uint32_t af0[2][4], af1[2][4], bf0[4][4], bf1[4][4];
#pragma unroll
            for (int mf = 0; mf < 2; ++mf) {
                LDMATRIX_X4(af0[mf], stb + SW128(arow[mf] + kb + abyte));
                LDMATRIX_X4(af1[mf], stb + 16384u + SW128(arow[mf] + kb + abyte));
            }
#pragma unroll
            for (int nf = 0; nf < 4; ++nf) {
                LDMATRIX_X4(bf0[nf], stb + 32768u + SW128(brow[nf] + kb + bbyte));
                LDMATRIX_X4(bf1[nf], stb + 49152u + SW128(brow[nf] + kb + bbyte));
            }
#pragma unroll
            for (int mf = 0; mf < 2; ++mf)
#pragma unroll
                for (int nf = 0; nf < 4; ++nf) {
                    MMA_BF16(acc[mf][2 * nf],     af0[mf], bf0[nf][0], bf0[nf][1]);
                    MMA_BF16(acc[mf][2 * nf + 1], af0[mf], bf0[nf][2], bf0[nf][3]);
                    MMA_BF16(acc[mf][2 * nf],     af0[mf], bf1[nf][0], bf1[nf][1]);
                    MMA_BF16(acc[mf][2 * nf + 1], af0[mf], bf1[nf][2], bf1[nf][3]);
                    MMA_BF16(acc[mf][2 * nf],     af1[mf], bf0[nf][0], bf0[nf][1]);
                    MMA_BF16(acc[mf][2 * nf + 1], af1[mf], bf0[nf][2], bf0[nf][3]);
                }
        }
        __syncthreads();
    }

#pragma unroll
    for (int mf = 0; mf < 2; ++mf) {
        size_t r = (size_t)row0 + wm + (mf << 4) + (lane >> 2);
#pragma unroll
        for (int nfr = 0; nfr < 8; ++nfr) {
            int n = col0 + wn + (nfr << 3) + ((lane & 3) << 1);
            float2 v0 = make_float2(acc[mf][nfr][0], acc[mf][nfr][1]);
            float2 v1 = make_float2(acc[mf][nfr][2], acc[mf][nfr][3]);
            if (RES) {
                float2 r0 = *(const float2*)(res + r * ldc + n);
                float2 r1 = *(const float2*)(res + (r + 8) * ldc + n);
                v0.x += r0.x; v0.y += r0.y; v1.x += r1.x; v1.y += r1.y;
            }
            *(float2*)(C + r * ldc + n) = v0;
            *(float2*)(C + (r + 8) * ldc + n) = v1;
        }
    }
}

// ---------------------------------------------------------------------------
// 3) Pointwise transform + repack time-major per (b,h).
//    Also precomputes kq = dot(q_norm, k_norm) into slot 193 (per-step scalar
//    used by the scan's o = W_old q + u*kq identity).
// ---------------------------------------------------------------------------
__device__ __forceinline__ float elu_p1(float v) {
    return v > 0.f ? v + 1.f : expf(v);
}
__global__ void __launch_bounds__(256) transform_kernel(
    const float* __restrict__ qkvb, float* __restrict__ packed)
{
    int r = blockIdx.x;
    int h = threadIdx.x >> 5;
    int lane = threadIdx.x & 31;
    int s = r >> 5, b = r & 31;
    const float* in = qkvb + (size_t)r * NQP + h * 193;

    float q1 = elu_p1(in[lane]),      q2 = elu_p1(in[lane + 32]);
    float k1 = elu_p1(in[64 + lane]), k2 = elu_p1(in[96 + lane]);
    float qs = q1 + q2, ks = k1 + k2;
    float ds = q1 * k1 + q2 * k2;
#pragma unroll
    for (int o = 16; o; o >>= 1) {
        qs += __shfl_xor_sync(0xffffffffu, qs, o);
        ks += __shfl_xor_sync(0xffffffffu, ks, o);
        ds += __shfl_xor_sync(0xffffffffu, ds, o);
    }
    float v1 = in[128 + lane], v2 = in[160 + lane];
    float bt = in[192];

    float* out = packed + ((size_t)(b * NH + h) * S_LEN + s) * PACK;
    float qi = 1.f / qs, ki = 1.f / ks;
    out[lane]       = q1 * qi;  out[lane + 32]  = q2 * qi;
    out[64 + lane]  = k1 * ki;  out[96 + lane]  = k2 * ki;
    out[128 + lane] = v1;       out[160 + lane] = v2;
    if (lane == 0) {
        out[192] = 1.f / (1.f + expf(-bt));
        out[193] = ds * qi * ki;     // kq = q_norm . k_norm
    }
}

// ---------------------------------------------------------------------------
// 4) Delta-rule scan: 128 threads, thread = (row, half), w[32] per thread.
//    Both dots run against OLD w (one pass, good ILP); o comes from the
//    identity o = W_old q + u * (k.q) with kq precomputed by transform.
//    Chunked prefetch: 1 barrier per 8 steps.
// ---------------------------------------------------------------------------
__global__ void __launch_bounds__(128) scan_kernel(
    const float* __restrict__ packed,
    __nv_bfloat16* __restrict__ o0, __nv_bfloat16* __restrict__ o1)
{
    __shared__ __align__(16) float sbuf[2][CH * PACK];
    int bh = blockIdx.x;
    int b = bh >> 3, h = bh & 7;
    int tid = threadIdx.x;
    int row = tid >> 1, half = tid & 1;

    const float4* base = (const float4*)(packed + (size_t)bh * S_LEN * PACK);
    float4 pre[4];
#pragma unroll
    for (int l = 0; l < 4; ++l) { int u = tid + (l << 7); if (u < 400) pre[l] = base[u]; }
#pragma unroll
    for (int l = 0; l < 4; ++l) { int u = tid + (l << 7); if (u < 400) ((float4*)sbuf[0])[u] = pre[l]; }

    float w[32];
#pragma unroll
    for (int j = 0; j < 32; ++j) w[j] = 0.f;
    __syncthreads();

    __nv_bfloat16* ob0 = o0 + (size_t)b * 512 + h * 64 + row;
    __nv_bfloat16* ob1 = o1 + (size_t)b * 512 + h * 64 + row;

    for (int c = 0; c < NCHUNK; ++c) {
        const float* cp0 = sbuf[c & 1];
        if (c + 1 < NCHUNK) {
            const float4* nb = base + (size_t)(c + 1) * (CH * PACK / 4);
#pragma unroll
            for (int l = 0; l < 4; ++l) { int u = tid + (l << 7); if (u < 400) pre[l] = nb[u]; }
        }
#pragma unroll
        for (int st = 0; st < CH; ++st) {
            const float* sp = cp0 + st * PACK;
            int t = (c << 3) + st;
            const float4* qp = (const float4*)(sp + (half << 5));
            const float4* kp = (const float4*)(sp + 64 + (half << 5));
            float kk[32];
            float pk = 0.f, pq = 0.f;
#pragma unroll
            for (int j4 = 0; j4 < 8; ++j4) {
                float4 k4 = kp[j4], q4 = qp[j4];
                kk[4*j4+0] = k4.x; kk[4*j4+1] = k4.y; kk[4*j4+2] = k4.z; kk[4*j4+3] = k4.w;
                pk += w[4*j4+0]*k4.x + w[4*j4+1]*k4.y + w[4*j4+2]*k4.z + w[4*j4+3]*k4.w;
                pq += w[4*j4+0]*q4.x + w[4*j4+1]*q4.y + w[4*j4+2]*q4.z + w[4*j4+3]*q4.w;
            }
            pk += __shfl_xor_sync(0xffffffffu, pk, 1);
            pq += __shfl_xor_sync(0xffffffffu, pq, 1);
            float u  = sp[192] * (sp[128 + row] - pk);
            float oi = pq + u * sp[193];
#pragma unroll
            for (int j = 0; j < 32; ++j) w[j] += u * kk[j];
            if (!half) {
                __nv_bfloat16 hi = __float2bfloat16(oi);
                __nv_bfloat16 lo = __float2bfloat16(oi - __bfloat162float(hi));
                ob0[(size_t)t * (BSZ * 512)] = hi;
                ob1[(size_t)t * (BSZ * 512)] = lo;
            }
        }
        if (c + 1 < NCHUNK) {
            float4* db = (float4*)sbuf[(c + 1) & 1];
#pragma unroll
            for (int l = 0; l < 4; ++l) { int u = tid + (l << 7); if (u < 400) db[u] = pre[l]; }
        }
        __syncthreads();
    }
}

// ---------------------------------------------------------------------------
// Launch
// ---------------------------------------------------------------------------
static const int SMEM_GEMM = 3 * STG_BYTES;   // 192KB

extern "C" void kernel_launch(void* const* d_in, const int* in_sizes, int n_in,
                              void* d_out, int out_size)
{
    const float* x     = (const float*)d_in[0];
    const float* gamma = (const float*)d_in[1];
    const float* beta  = (const float*)d_in[2];
    const float* wslow = (const float*)d_in[3];
    const float* wout  = (const float*)d_in[4];
    float* out = (float*)d_out;

    __nv_bfloat16 *h0, *h1, *B0, *B1, *W0, *W1, *o0, *o1;
    float *qkvb, *packed;
    cudaGetSymbolAddress((void**)&h0, g_h0);
    cudaGetSymbolAddress((void**)&h1, g_h1);
    cudaGetSymbolAddress((void**)&qkvb, g_qkvb);
    cudaGetSymbolAddress((void**)&B0, g_B0);
    cudaGetSymbolAddress((void**)&B1, g_B1);
    cudaGetSymbolAddress((void**)&W0, g_W0);
    cudaGetSymbolAddress((void**)&W1, g_W1);
    cudaGetSymbolAddress((void**)&packed, g_packed);
    cudaGetSymbolAddress((void**)&o0, g_o0);
    cudaGetSymbolAddress((void**)&o1, g_o1);

    cudaFuncSetAttribute(gemm_mma<false>, cudaFuncAttributeMaxDynamicSharedMemorySize, SMEM_GEMM);
    cudaFuncSetAttribute(gemm_mma<true>,  cudaFuncAttributeMaxDynamicSharedMemorySize, SMEM_GEMM);

    ln_kernel<<<NROWS / 8, 256>>>(x, gamma, beta, h0, h1);
    conv_wslow<<<(NQP * CIN + 255) / 256, 256>>>(wslow, B0, B1);
    conv_wout<<<(CIN * CIN + 255) / 256, 256>>>(wout, W0, W1);
    gemm_mma<false><<<dim3(NQP / 128, NROWS / 128), 256, SMEM_GEMM>>>(
        h0, h1, B0, B1, nullptr, qkvb, NQP);
    transform_kernel<<<NROWS, 256>>>(qkvb, packed);
    scan_kernel<<<BSZ * NH, 128>>>(packed, o0, o1);
    gemm_mma<true><<<dim3(4, NROWS / 128), 256, SMEM_GEMM>>>(
        o0, o1, W0, W1, x, out, CIN);
}